// round 5
// baseline (speedup 1.0000x reference)
#include <cuda_runtime.h>
#include <cuda_bf16.h>
#include <cstdint>

// Problem constants (fixed by dataset: B=4, S=2048, D=1024, O=1024, C=8)
#define T_TOK 8192
#define DIM_D 1024
#define DIM_O 1024
#define N_CAT 8

#define TM 128
#define TN 128
#define BK 128                       // K per smem stage (128 int8 = 128B rows)
#define NCHUNK (DIM_D / BK)          // 8
#define MAX_TILES (T_TOK / TM + N_CAT)

// ---------------- device scratch (no allocation allowed) --------------------
__device__ int g_perm[T_TOK];
__device__ int g_tile_cat[MAX_TILES];
__device__ int g_tile_row[MAX_TILES];
__device__ int g_tile_rows[MAX_TILES];
__device__ int g_n_tiles;
__device__ float g_sx[T_TOK];             // per sorted-row x scale
__device__ float g_sw[N_CAT * DIM_O];     // per (cat, o) w scale

// int8 dual-limb operands. A padded by TM rows: padding never written ->
// stays zero (module zero init) -> safe for partial tiles.
__device__ signed char g_Qxh[(T_TOK + TM) * DIM_D];
__device__ signed char g_Qxl[(T_TOK + TM) * DIM_D];
__device__ signed char g_Qwh[N_CAT * DIM_O * DIM_D];   // [c][o][d]
__device__ signed char g_Qwl[N_CAT * DIM_O * DIM_D];

// ---------------- PTX helpers (baseline sm_80/75 features only) -------------
__device__ __forceinline__ uint32_t smem_u32(const void* p) {
    uint32_t a;
    asm("{ .reg .u64 t; cvta.to.shared.u64 t, %1; cvt.u32.u64 %0, t; }" : "=r"(a) : "l"(p));
    return a;
}

#define CP_ASYNC16(dst, src) \
    asm volatile("cp.async.cg.shared.global [%0], [%1], 16;" :: "r"(dst), "l"(src) : "memory")
#define CP_COMMIT() asm volatile("cp.async.commit_group;" ::: "memory")
#define CP_WAIT0()  asm volatile("cp.async.wait_group 0;" ::: "memory")
#define CP_WAIT1()  asm volatile("cp.async.wait_group 1;" ::: "memory")

#define LDSM4(r0, r1, r2, r3, addr)                                              \
    asm volatile("ldmatrix.sync.aligned.m8n8.x4.shared.b16 {%0,%1,%2,%3}, [%4];" \
                 : "=r"(r0), "=r"(r1), "=r"(r2), "=r"(r3) : "r"(addr))

#define MMA_S8(c, a, b)                                                          \
    asm volatile("mma.sync.aligned.m16n8k32.row.col.s32.s8.s8.s32 "              \
                 "{%0,%1,%2,%3}, {%4,%5,%6,%7}, {%8,%9}, {%0,%1,%2,%3};"         \
                 : "+r"((c)[0]), "+r"((c)[1]), "+r"((c)[2]), "+r"((c)[3])        \
                 : "r"((a)[0]), "r"((a)[1]), "r"((a)[2]), "r"((a)[3]),           \
                   "r"((b)[0]), "r"((b)[1]))

__device__ __forceinline__ uint32_t sw128(uint32_t off) {
    return off ^ ((off >> 3) & 0x70);
}

__device__ __forceinline__ uint32_t pack4(int a, int b, int c, int d) {
    return (uint32_t)(a & 0xFF) | ((uint32_t)(b & 0xFF) << 8) |
           ((uint32_t)(c & 0xFF) << 16) | ((uint32_t)(d & 0xFF) << 24);
}

// ---------------- fused setup: hist + scan + tiles + perm (one CTA) ---------
__global__ void k_setup(const int* __restrict__ cid) {
    __shared__ int s_cnt[N_CAT], s_cur[N_CAT], s_off[N_CAT];
    const int tid = threadIdx.x;    // 1024 threads
    if (tid < N_CAT) { s_cnt[tid] = 0; s_cur[tid] = 0; }
    __syncthreads();

    int cl[8];
#pragma unroll
    for (int i = 0; i < 8; i++) {
        cl[i] = cid[tid + i * 1024] & (N_CAT - 1);
        atomicAdd(&s_cnt[cl[i]], 1);
    }
    __syncthreads();

    if (tid == 0) {
        int off = 0, nt = 0;
        for (int c = 0; c < N_CAT; c++) {
            s_off[c] = off;
            int cnt = s_cnt[c];
            for (int r = 0; r < cnt; r += TM) {
                g_tile_cat[nt]  = c;
                g_tile_row[nt]  = off + r;
                g_tile_rows[nt] = (cnt - r < TM) ? (cnt - r) : TM;
                nt++;
            }
            off += cnt;
        }
        g_n_tiles = nt;
    }
    __syncthreads();

#pragma unroll
    for (int i = 0; i < 8; i++) {
        int c = cl[i];
        int pos = s_off[c] + atomicAdd(&s_cur[c], 1);
        g_perm[pos] = tid + i * 1024;
    }
}

// ---------------- x -> sorted-gathered int8 limbs (fused row max) -----------
__global__ void k_conv_x(const float* __restrict__ x) {
    __shared__ float red[8];
    __shared__ float s_inv;
    const int p   = blockIdx.x;         // sorted position
    const int tok = g_perm[p];
    const int tid = threadIdx.x;        // 256

    float4 v = *reinterpret_cast<const float4*>(x + (size_t)tok * DIM_D + tid * 4);
    float m = fmaxf(fmaxf(fabsf(v.x), fabsf(v.y)), fmaxf(fabsf(v.z), fabsf(v.w)));
#pragma unroll
    for (int o = 16; o; o >>= 1) m = fmaxf(m, __shfl_xor_sync(0xFFFFFFFFu, m, o));
    if ((tid & 31) == 0) red[tid >> 5] = m;
    __syncthreads();
    if (tid == 0) {
        float M = red[0];
#pragma unroll
        for (int i = 1; i < 8; i++) M = fmaxf(M, red[i]);
        M = fmaxf(M, 1e-20f);
        g_sx[p] = M / 8000.f;
        s_inv   = 8000.f / M;
    }
    __syncthreads();
    const float inv = s_inv;

    int q0 = __float2int_rn(v.x * inv), h0 = __float2int_rn(v.x * inv * 0.0078125f);
    int q1 = __float2int_rn(v.y * inv), h1 = __float2int_rn(v.y * inv * 0.0078125f);
    int q2 = __float2int_rn(v.z * inv), h2 = __float2int_rn(v.z * inv * 0.0078125f);
    int q3 = __float2int_rn(v.w * inv), h3 = __float2int_rn(v.w * inv * 0.0078125f);

    *reinterpret_cast<uint32_t*>(&g_Qxh[(size_t)p * DIM_D + tid * 4]) = pack4(h0, h1, h2, h3);
    *reinterpret_cast<uint32_t*>(&g_Qxl[(size_t)p * DIM_D + tid * 4]) =
        pack4(q0 - 128 * h0, q1 - 128 * h1, q2 - 128 * h2, q3 - 128 * h3);
}

// ---------------- w [c][d][o] -> int8 limbs [c][o][d] + column scales --------
__global__ void k_conv_w(const float* __restrict__ w) {
    __shared__ float t[32][33];
    __shared__ float s_scale[32];
    const int cat = blockIdx.y;
    const int o0  = blockIdx.x * 32;
    const int tx = threadIdx.x, ty = threadIdx.y;   // (32, 8)

    const float* base = w + ((size_t)cat << 20) + o0;

    // pass 1: column max over d
    float m = 0.f;
    for (int d = ty; d < DIM_D; d += 8)
        m = fmaxf(m, fabsf(base[(size_t)d * DIM_O + tx]));
    t[ty][tx] = m;
    __syncthreads();
    if (ty == 0) {
        float M = t[0][tx];
#pragma unroll
        for (int i = 1; i < 8; i++) M = fmaxf(M, t[i][tx]);
        M = fmaxf(M, 1e-20f);
        g_sw[cat * DIM_O + o0 + tx] = M / 8000.f;
        s_scale[tx] = 8000.f / M;
    }
    __syncthreads();

    // pass 2: quantize + transpose through smem
    for (int d0 = 0; d0 < DIM_D; d0 += 32) {
#pragma unroll
        for (int i = 0; i < 4; i++)
            t[ty + 8 * i][tx] = base[(size_t)(d0 + ty + 8 * i) * DIM_O + tx];
        __syncthreads();
        size_t dst = ((size_t)cat << 20) + (size_t)o0 * DIM_D + d0;
#pragma unroll
        for (int i = 0; i < 4; i++) {
            int ol = ty + 8 * i;
            float v = t[tx][ol] * s_scale[ol];     // w[d0+tx][o0+ol] scaled
            int q = __float2int_rn(v);
            int h = __float2int_rn(v * 0.0078125f);
            g_Qwh[dst + (size_t)ol * DIM_D + tx] = (signed char)h;
            g_Qwl[dst + (size_t)ol * DIM_D + tx] = (signed char)(q - 128 * h);
        }
        __syncthreads();
    }
}

// ---------------- int8 dual-limb grouped GEMM --------------------------------
// smem: [0..512) toks, [512..1024) bias, [1024..1536) sx, [1536..2048) sw,
//       [2048..) 2 stages of {Qxh 16K | Qxl 16K | Qwh 16K | Qwl 16K}
#define SM_TOKS   0
#define SM_BIAS   512
#define SM_SX     1024
#define SM_SW     1536
#define SM_STAGE  2048
#define PART_BYTES  16384
#define STAGE_BYTES 65536
#define SMEM_TOTAL (SM_STAGE + 2 * STAGE_BYTES)

__global__ __launch_bounds__(256, 1)
void k_gemm_i8(const float* __restrict__ bias, float* __restrict__ out) {
    const int tile = blockIdx.x;
    if (tile >= g_n_tiles) return;

    const int cat       = g_tile_cat[tile] & (N_CAT - 1);
    const int row_start = g_tile_row[tile];
    const int rows      = g_tile_rows[tile];
    const int n0        = blockIdx.y * TN;

    extern __shared__ char smem[];
    const uint32_t sm = smem_u32(smem);
    const int tid  = threadIdx.x;
    const int wid  = tid >> 5;
    const int lane = tid & 31;
    const int wm   = wid >> 2;        // 0..1 -> m offset wm*64
    const int wn   = wid & 3;         // 0..3 -> n offset wn*32

    int*   toks   = reinterpret_cast<int*>(smem + SM_TOKS);
    float* bias_s = reinterpret_cast<float*>(smem + SM_BIAS);
    float* sx_s   = reinterpret_cast<float*>(smem + SM_SX);
    float* sw_s   = reinterpret_cast<float*>(smem + SM_SW);
    if (tid < TM) {
        toks[tid] = (tid < rows) ? g_perm[row_start + tid] : -1;
        sx_s[tid] = (tid < rows) ? g_sx[row_start + tid] : 0.f;
    } else {
        bias_s[tid - 128] = bias[cat * DIM_O + n0 + tid - 128];
        sw_s[tid - 128]   = g_sw[cat * DIM_O + n0 + tid - 128];
    }

    // global row bases (int8 rows = 1024B)
    const char* gbase[4];
    gbase[0] = reinterpret_cast<const char*>(g_Qxh) + (size_t)row_start * DIM_D;
    gbase[1] = reinterpret_cast<const char*>(g_Qxl) + (size_t)row_start * DIM_D;
    gbase[2] = reinterpret_cast<const char*>(g_Qwh) + (((size_t)cat << 10) + n0) * DIM_D;
    gbase[3] = reinterpret_cast<const char*>(g_Qwl) + (((size_t)cat << 10) + n0) * DIM_D;

    // chunk loader: 4 arrays x 128 rows x 8 x 16B = 4096 cp.async, 16/thread
#define ISSUE_CHUNK(kc, buf)                                                        \
    _Pragma("unroll")                                                               \
    for (int t = 0; t < 16; t++) {                                                  \
        int idx = tid + t * 256;                                                    \
        int arr = idx >> 10;                                                        \
        int r   = (idx >> 3) & 127;                                                 \
        int c   = idx & 7;                                                          \
        const char* src = gbase[arr] + (size_t)r * DIM_D + (size_t)(kc) * 128 + c * 16; \
        uint32_t dst = sm + SM_STAGE + (buf) * STAGE_BYTES + arr * PART_BYTES       \
                     + sw128((uint32_t)(r * 128 + c * 16));                         \
        CP_ASYNC16(dst, src);                                                       \
    }                                                                               \
    CP_COMMIT();

    int acc1[4][4][4], acc2[4][4][4];
#pragma unroll
    for (int i = 0; i < 4; i++)
#pragma unroll
        for (int j = 0; j < 4; j++)
#pragma unroll
            for (int k = 0; k < 4; k++) { acc1[i][j][k] = 0; acc2[i][j][k] = 0; }

    ISSUE_CHUNK(0, 0);
    ISSUE_CHUNK(1, 1);

    const int fr_row = lane & 15;
    const int fr_kb  = lane >> 4;

    for (int it = 0; it < NCHUNK; it++) {
        if (it < NCHUNK - 1) { CP_WAIT1(); } else { CP_WAIT0(); }
        __syncthreads();

        const uint32_t st   = sm + SM_STAGE + (it & 1) * STAGE_BYTES;
        const uint32_t stAh = st;
        const uint32_t stAl = st + PART_BYTES;
        const uint32_t stBh = st + 2 * PART_BYTES;
        const uint32_t stBl = st + 3 * PART_BYTES;

#pragma unroll
        for (int ks = 0; ks < 4; ks++) {       // each kstep = 32 int8 = 32B
            const uint32_t kcol = (uint32_t)((ks * 2 + fr_kb) * 16);

            uint32_t ah[4][4], al[4][4], bh[4][2], bl[4][2];
#pragma unroll
            for (int mi = 0; mi < 4; mi++) {
                uint32_t a = sw128((uint32_t)((wm * 64 + mi * 16 + fr_row) * 128) + kcol);
                LDSM4(ah[mi][0], ah[mi][1], ah[mi][2], ah[mi][3], stAh + a);
                LDSM4(al[mi][0], al[mi][1], al[mi][2], al[mi][3], stAl + a);
            }
#pragma unroll
            for (int pj = 0; pj < 2; pj++) {
                uint32_t a = sw128((uint32_t)((wn * 32 + pj * 16 + fr_row) * 128) + kcol);
                uint32_t r0, r1, r2, r3;
                LDSM4(r0, r1, r2, r3, stBh + a);
                bh[pj * 2][0]     = r0; bh[pj * 2][1]     = r2;
                bh[pj * 2 + 1][0] = r1; bh[pj * 2 + 1][1] = r3;
                LDSM4(r0, r1, r2, r3, stBl + a);
                bl[pj * 2][0]     = r0; bl[pj * 2][1]     = r2;
                bl[pj * 2 + 1][0] = r1; bl[pj * 2 + 1][1] = r3;
            }

#pragma unroll
            for (int mi = 0; mi < 4; mi++)
#pragma unroll
                for (int ni = 0; ni < 4; ni++) {
                    MMA_S8(acc1[mi][ni], ah[mi], bh[ni]);   // hi*hi  (weight 16384)
                    MMA_S8(acc2[mi][ni], ah[mi], bl[ni]);   // hi*lo  (weight 128)
                    MMA_S8(acc2[mi][ni], al[mi], bh[ni]);   // lo*hi  (weight 128)
                }
        }

        __syncthreads();
        if (it + 2 < NCHUNK) { ISSUE_CHUNK(it + 2, it & 1); }
    }

    // ---- epilogue: dequant + bias + scatter
#pragma unroll
    for (int mi = 0; mi < 4; mi++) {
        int m0   = wm * 64 + mi * 16 + (lane >> 2);
        int tok0 = toks[m0];
        int tok1 = toks[m0 + 8];
        float sx0 = sx_s[m0];
        float sx1 = sx_s[m0 + 8];
#pragma unroll
        for (int ni = 0; ni < 4; ni++) {
            int col = wn * 32 + ni * 8 + 2 * (lane & 3);
            float b0 = bias_s[col],  b1 = bias_s[col + 1];
            float w0 = sw_s[col],    w1 = sw_s[col + 1];
            if (tok0 >= 0) {
                float f0 = fmaf(16384.f, (float)acc1[mi][ni][0], 128.f * (float)acc2[mi][ni][0]);
                float f1 = fmaf(16384.f, (float)acc1[mi][ni][1], 128.f * (float)acc2[mi][ni][1]);
                float2 v = make_float2(fmaf(f0, sx0 * w0, b0), fmaf(f1, sx0 * w1, b1));
                *reinterpret_cast<float2*>(out + (size_t)tok0 * DIM_O + n0 + col) = v;
            }
            if (tok1 >= 0) {
                float f2 = fmaf(16384.f, (float)acc1[mi][ni][2], 128.f * (float)acc2[mi][ni][2]);
                float f3 = fmaf(16384.f, (float)acc1[mi][ni][3], 128.f * (float)acc2[mi][ni][3]);
                float2 v = make_float2(fmaf(f2, sx1 * w0, b0), fmaf(f3, sx1 * w1, b1));
                *reinterpret_cast<float2*>(out + (size_t)tok1 * DIM_O + n0 + col) = v;
            }
        }
    }
}

// ---------------- launch --------------------------------------------------------
extern "C" void kernel_launch(void* const* d_in, const int* in_sizes, int n_in,
                              void* d_out, int out_size) {
    const float* x    = (const float*)d_in[0];   // [T, D] fp32
    const int*   cid  = (const int*)d_in[1];     // [T] int32
    const float* wgt  = (const float*)d_in[2];   // [C, D, O] fp32
    const float* bias = (const float*)d_in[3];   // [C, O] fp32
    float*       out  = (float*)d_out;           // [T, O] fp32

    (void)in_sizes; (void)n_in; (void)out_size;

    cudaFuncSetAttribute(k_gemm_i8, cudaFuncAttributeMaxDynamicSharedMemorySize, SMEM_TOTAL);

    k_setup<<<1, 1024>>>(cid);
    k_conv_x<<<T_TOK, 256>>>(x);
    k_conv_w<<<dim3(DIM_O / 32, N_CAT), dim3(32, 8)>>>(wgt);

    dim3 grid(MAX_TILES, DIM_O / TN);   // 72 x 8; CTAs past g_n_tiles exit early
    k_gemm_i8<<<grid, 256, SMEM_TOTAL>>>(bias, out);
}

// round 6
// speedup vs baseline: 4.8436x; 4.8436x over previous
#include <cuda_runtime.h>
#include <cuda_fp16.h>
#include <cstdint>

// Problem constants (fixed by dataset: B=4, S=2048, D=1024, O=1024, C=8)
#define T_TOK 8192
#define DIM_D 1024
#define DIM_O 1024
#define N_CAT 8

#define TM 128
#define TN 128
#define BK 64                        // K per smem stage (64 fp16 = 128B rows)
#define NCHUNK (DIM_D / BK)          // 16
#define MAX_TILES (T_TOK / TM + N_CAT)

// ---------------- device scratch (no allocation allowed) --------------------
__device__ int g_perm[T_TOK];
__device__ int g_tile_cat[MAX_TILES];
__device__ int g_tile_row[MAX_TILES];
__device__ int g_tile_rows[MAX_TILES];
__device__ int g_n_tiles;

// fp16 operands. A padded by TM rows: padding never written -> stays zero
// (module zero init) -> safe for partial tiles.
__device__ __half g_Xh[(T_TOK + TM) * DIM_D];
__device__ __half g_Wh[N_CAT * DIM_O * DIM_D];   // transposed: [c][o][d]

// ---------------- PTX helpers (baseline sm_80/75 features only) -------------
__device__ __forceinline__ uint32_t smem_u32(const void* p) {
    uint32_t a;
    asm("{ .reg .u64 t; cvta.to.shared.u64 t, %1; cvt.u32.u64 %0, t; }" : "=r"(a) : "l"(p));
    return a;
}

#define CP_ASYNC16(dst, src) \
    asm volatile("cp.async.cg.shared.global [%0], [%1], 16;" :: "r"(dst), "l"(src) : "memory")
#define CP_COMMIT() asm volatile("cp.async.commit_group;" ::: "memory")
#define CP_WAIT0()  asm volatile("cp.async.wait_group 0;" ::: "memory")
#define CP_WAIT1()  asm volatile("cp.async.wait_group 1;" ::: "memory")

#define LDSM4(r0, r1, r2, r3, addr)                                              \
    asm volatile("ldmatrix.sync.aligned.m8n8.x4.shared.b16 {%0,%1,%2,%3}, [%4];" \
                 : "=r"(r0), "=r"(r1), "=r"(r2), "=r"(r3) : "r"(addr))

#define MMA_F16(c, a, b)                                                         \
    asm volatile("mma.sync.aligned.m16n8k16.row.col.f32.f16.f16.f32 "            \
                 "{%0,%1,%2,%3}, {%4,%5,%6,%7}, {%8,%9}, {%0,%1,%2,%3};"         \
                 : "+f"((c)[0]), "+f"((c)[1]), "+f"((c)[2]), "+f"((c)[3])        \
                 : "r"((a)[0]), "r"((a)[1]), "r"((a)[2]), "r"((a)[3]),           \
                   "r"((b)[0]), "r"((b)[1]))

__device__ __forceinline__ uint32_t sw128(uint32_t off) {
    return off ^ ((off >> 3) & 0x70);
}

// ---------------- fused setup: hist + scan + tiles + perm (one CTA) ---------
__global__ void k_setup(const int* __restrict__ cid) {
    __shared__ int s_cnt[N_CAT], s_cur[N_CAT], s_off[N_CAT];
    const int tid = threadIdx.x;    // 1024 threads
    if (tid < N_CAT) { s_cnt[tid] = 0; s_cur[tid] = 0; }
    __syncthreads();

    int cl[8];
#pragma unroll
    for (int i = 0; i < 8; i++) {
        cl[i] = cid[tid + i * 1024] & (N_CAT - 1);
        atomicAdd(&s_cnt[cl[i]], 1);
    }
    __syncthreads();

    if (tid == 0) {
        int off = 0, nt = 0;
        for (int c = 0; c < N_CAT; c++) {
            s_off[c] = off;
            int cnt = s_cnt[c];
            for (int r = 0; r < cnt; r += TM) {
                g_tile_cat[nt]  = c;
                g_tile_row[nt]  = off + r;
                g_tile_rows[nt] = (cnt - r < TM) ? (cnt - r) : TM;
                nt++;
            }
            off += cnt;
        }
        g_n_tiles = nt;
    }
    __syncthreads();

#pragma unroll
    for (int i = 0; i < 8; i++) {
        int c = cl[i];
        int pos = s_off[c] + atomicAdd(&s_cur[c], 1);
        g_perm[pos] = tid + i * 1024;
    }
}

// ---------------- x -> sorted-gathered fp16 ---------------------------------
__global__ void k_conv_x(const float* __restrict__ x) {
    const int p   = blockIdx.x;         // sorted position
    const int tok = g_perm[p];
    const int c   = threadIdx.x * 4;    // 256 threads
    float4 v = *reinterpret_cast<const float4*>(x + (size_t)tok * DIM_D + c);

    __half2 a = __floats2half2_rn(v.x, v.y);
    __half2 b = __floats2half2_rn(v.z, v.w);
    uint2 u;
    u.x = *reinterpret_cast<uint32_t*>(&a);
    u.y = *reinterpret_cast<uint32_t*>(&b);
    *reinterpret_cast<uint2*>(&g_Xh[(size_t)p * DIM_D + c]) = u;
}

// ---------------- w [c][d][o] fp32 -> [c][o][d] fp16 (smem transpose) -------
__global__ void k_conv_w(const float* __restrict__ w) {
    __shared__ float t[32][33];
    const int cat = blockIdx.z;
    const int o0  = blockIdx.x * 32;
    const int d0  = blockIdx.y * 32;
    const int tx = threadIdx.x, ty = threadIdx.y;   // (32, 8)

    const float* src = w + ((size_t)cat << 20) + (size_t)d0 * DIM_O + o0;
#pragma unroll
    for (int i = 0; i < 4; i++)
        t[ty + 8 * i][tx] = src[(size_t)(ty + 8 * i) * DIM_O + tx];
    __syncthreads();

    size_t dst = ((size_t)cat << 20) + (size_t)o0 * DIM_D + d0;
#pragma unroll
    for (int i = 0; i < 4; i++)
        g_Wh[dst + (size_t)(ty + 8 * i) * DIM_D + tx] = __float2half_rn(t[tx][ty + 8 * i]);
}

// ---------------- fp16 mma.sync grouped GEMM --------------------------------
// smem: [0..512) toks, [512..1024) bias, [2048..) 3 stages of {A 16K | B 16K}
#define SM_TOKS   0
#define SM_BIAS   512
#define SM_STAGE  2048
#define PART_BYTES  16384
#define STAGE_BYTES 32768
#define NSTAGE 3
#define SMEM_TOTAL (SM_STAGE + NSTAGE * STAGE_BYTES)

__global__ __launch_bounds__(256, 2)
void k_gemm_f16(const float* __restrict__ bias, float* __restrict__ out) {
    const int tile = blockIdx.x;
    if (tile >= g_n_tiles) return;

    const int cat       = g_tile_cat[tile] & (N_CAT - 1);
    const int row_start = g_tile_row[tile];
    const int rows      = g_tile_rows[tile];
    const int n0        = blockIdx.y * TN;

    extern __shared__ char smem[];
    const uint32_t sm = smem_u32(smem);
    const int tid  = threadIdx.x;
    const int wid  = tid >> 5;
    const int lane = tid & 31;
    const int wm   = wid >> 2;        // 0..1 -> m offset wm*64
    const int wn   = wid & 3;         // 0..3 -> n offset wn*32

    int*   toks   = reinterpret_cast<int*>(smem + SM_TOKS);
    float* bias_s = reinterpret_cast<float*>(smem + SM_BIAS);
    if (tid < TM) toks[tid] = (tid < rows) ? g_perm[row_start + tid] : -1;
    if (tid >= 128) bias_s[tid - 128] = bias[cat * DIM_O + n0 + tid - 128];

    // global row bases (fp16 rows = 2048B)
    const char* gA = reinterpret_cast<const char*>(g_Xh) + (size_t)row_start * 2048;
    const char* gB = reinterpret_cast<const char*>(g_Wh) + (((size_t)cat << 10) + n0) * 2048;

    // chunk loader: 2 arrays x 128 rows x 8 x 16B = 2048 cp.async, 8/thread
#define ISSUE_CHUNK(kc, buf)                                                        \
    _Pragma("unroll")                                                               \
    for (int t = 0; t < 8; t++) {                                                   \
        int idx = tid + t * 256;                                                    \
        int arr = idx >> 10;                                                        \
        int r   = (idx >> 3) & 127;                                                 \
        int c   = idx & 7;                                                          \
        const char* src = ((arr) ? gB : gA) + (size_t)r * 2048 + (size_t)(kc) * 128 + c * 16; \
        uint32_t dst = sm + SM_STAGE + (buf) * STAGE_BYTES + arr * PART_BYTES       \
                     + sw128((uint32_t)(r * 128 + c * 16));                         \
        CP_ASYNC16(dst, src);                                                       \
    }                                                                               \
    CP_COMMIT();

    float acc[4][4][4];
#pragma unroll
    for (int i = 0; i < 4; i++)
#pragma unroll
        for (int j = 0; j < 4; j++)
#pragma unroll
            for (int k = 0; k < 4; k++) acc[i][j][k] = 0.f;

    // prologue: 2 chunks in flight, 3 buffers
    ISSUE_CHUNK(0, 0);
    ISSUE_CHUNK(1, 1);

    const int fr_row = lane & 15;
    const int fr_kb  = lane >> 4;

    for (int it = 0; it < NCHUNK; it++) {
        if (it < NCHUNK - 1) { CP_WAIT1(); } else { CP_WAIT0(); }
        __syncthreads();   // chunk `it` visible to all; stage (it+2)%3 free

        if (it + 2 < NCHUNK) { ISSUE_CHUNK(it + 2, (it + 2) % NSTAGE); }

        const uint32_t st  = sm + SM_STAGE + (it % NSTAGE) * STAGE_BYTES;
        const uint32_t stA = st;
        const uint32_t stB = st + PART_BYTES;

#pragma unroll
        for (int ks = 0; ks < 4; ks++) {
            const uint32_t kcol = (uint32_t)((ks * 2 + fr_kb) * 16);

            uint32_t a[4][4], b[4][2];
#pragma unroll
            for (int mi = 0; mi < 4; mi++) {
                uint32_t ad = sw128((uint32_t)((wm * 64 + mi * 16 + fr_row) * 128) + kcol);
                LDSM4(a[mi][0], a[mi][1], a[mi][2], a[mi][3], stA + ad);
            }
#pragma unroll
            for (int pj = 0; pj < 2; pj++) {
                uint32_t ad = sw128((uint32_t)((wn * 32 + pj * 16 + fr_row) * 128) + kcol);
                uint32_t r0, r1, r2, r3;
                LDSM4(r0, r1, r2, r3, stB + ad);
                b[pj * 2][0]     = r0; b[pj * 2][1]     = r2;
                b[pj * 2 + 1][0] = r1; b[pj * 2 + 1][1] = r3;
            }

#pragma unroll
            for (int mi = 0; mi < 4; mi++)
#pragma unroll
                for (int ni = 0; ni < 4; ni++)
                    MMA_F16(acc[mi][ni], a[mi], b[ni]);
        }
    }

    // ---- epilogue: bias + scatter (C frag: rows t/4, t/4+8; cols 2(t%4)+{0,1})
#pragma unroll
    for (int mi = 0; mi < 4; mi++) {
        int m0   = wm * 64 + mi * 16 + (lane >> 2);
        int tok0 = toks[m0];
        int tok1 = toks[m0 + 8];
#pragma unroll
        for (int ni = 0; ni < 4; ni++) {
            int col = wn * 32 + ni * 8 + 2 * (lane & 3);
            float b0 = bias_s[col], b1 = bias_s[col + 1];
            if (tok0 >= 0) {
                float2 v = make_float2(acc[mi][ni][0] + b0, acc[mi][ni][1] + b1);
                *reinterpret_cast<float2*>(out + (size_t)tok0 * DIM_O + n0 + col) = v;
            }
            if (tok1 >= 0) {
                float2 v = make_float2(acc[mi][ni][2] + b0, acc[mi][ni][3] + b1);
                *reinterpret_cast<float2*>(out + (size_t)tok1 * DIM_O + n0 + col) = v;
            }
        }
    }
}

// ---------------- launch --------------------------------------------------------
extern "C" void kernel_launch(void* const* d_in, const int* in_sizes, int n_in,
                              void* d_out, int out_size) {
    const float* x    = (const float*)d_in[0];   // [T, D] fp32
    const int*   cid  = (const int*)d_in[1];     // [T] int32
    const float* wgt  = (const float*)d_in[2];   // [C, D, O] fp32
    const float* bias = (const float*)d_in[3];   // [C, O] fp32
    float*       out  = (float*)d_out;           // [T, O] fp32

    (void)in_sizes; (void)n_in; (void)out_size;

    cudaFuncSetAttribute(k_gemm_f16, cudaFuncAttributeMaxDynamicSharedMemorySize, SMEM_TOTAL);

    k_setup<<<1, 1024>>>(cid);
    k_conv_x<<<T_TOK, 256>>>(x);
    k_conv_w<<<dim3(DIM_O / 32, DIM_D / 32, N_CAT), dim3(32, 8)>>>(wgt);

    dim3 grid(MAX_TILES, DIM_O / TN);   // 72 x 8; CTAs past g_n_tiles exit early
    k_gemm_f16<<<grid, 256, SMEM_TOTAL>>>(bias, out);
}